// round 13
// baseline (speedup 1.0000x reference)
#include <cuda_runtime.h>
#include <cuda_bf16.h>
#include <cstdint>

#define BATCH 2048
#define NIN   2048
#define NG    8192
#define NCOL  16384  // NG*2

// ---------------------------------------------------------------------------
// Scratch (static device globals -- allocation-free rule)
__device__ __align__(1024) __nv_bfloat16 g_Pt[(size_t)NCOL * NIN];  // exp(c)^T, 67 MB
__device__ __align__(1024) __nv_bfloat16 g_xb[(size_t)BATCH * NIN]; // x bf16, 8 MB
__device__ float  g_spart[8 * NCOL];
__device__ float4 g_coef4[NG];     // (alpha, beta, gamma, delta) per gate

__device__ __forceinline__ uint32_t smem_to_u32(const void* p) {
    uint32_t a;
    asm("{ .reg .u64 t; cvta.to.shared.u64 t, %1; cvt.u32.u64 %0, t; }" : "=r"(a) : "l"(p));
    return a;
}

// ---------------------------------------------------------------------------
// Kernel 1: fused Pt=exp(c)^T (+ partial sums), x->bf16 cast, gate coefficients.
#define NB_EXP  4096   // (NCOL/32) * (NIN/256)
#define NB_XCVT 16384  // BATCH*NIN/256
__global__ __launch_bounds__(256) void k_fuse(const float* __restrict__ c,
                                              const float* __restrict__ x,
                                              const float* __restrict__ w) {
    int b = blockIdx.x;
    if (b < NB_EXP) {
        __shared__ __nv_bfloat16 sm[256][34];
        __shared__ float ssum[8][32];
        const int bx = b & 511, by = b >> 9;
        const int tj = threadIdx.x & 31;
        const int ti = threadIdx.x >> 5;
        const int j0 = bx * 32;
        const int i0 = by * 256;

        float s = 0.f;
#pragma unroll 4
        for (int it = 0; it < 32; ++it) {
            int il = ti + 8 * it;
            float e = __expf(c[(size_t)(i0 + il) * NCOL + j0 + tj]);
            sm[il][tj] = __float2bfloat16(e);
            s += e;
        }
        ssum[ti][tj] = s;
        __syncthreads();
        if (ti == 0) {
            float t = 0.f;
#pragma unroll
            for (int k = 0; k < 8; ++k) t += ssum[k][tj];
            g_spart[by * NCOL + j0 + tj] = t;
        }
#pragma unroll 4
        for (int jj = 0; jj < 32; ++jj) {
            g_Pt[(size_t)(j0 + jj) * NIN + i0 + threadIdx.x] = sm[threadIdx.x][jj];
        }
        return;
    }
    if (b < NB_EXP + NB_XCVT) {
        int i = (b - NB_EXP) * 256 + threadIdx.x;
        g_xb[i] = __float2bfloat16(x[i]);
        return;
    }
    int g = (b - NB_EXP - NB_XCVT) * 256 + threadIdx.x;
    if (g >= NG) return;
    float v[16];
    float m = -1e30f;
#pragma unroll
    for (int k = 0; k < 16; ++k) { v[k] = w[k * NG + g]; m = fmaxf(m, v[k]); }
    float sum = 0.f;
#pragma unroll
    for (int k = 0; k < 16; ++k) { v[k] = __expf(v[k] - m); sum += v[k]; }
    float inv = 1.f / sum;
#pragma unroll
    for (int k = 0; k < 16; ++k) v[k] *= inv;

    float al = v[8]+v[9]+v[10]+v[11]+v[12]+v[13]+v[14]+v[15];
    float be = v[2]+v[3]+v[6]+v[7] - v[8]-v[9]-v[12]-v[13];
    float ga = v[4]+v[5]+v[6]+v[7] - v[8]-v[9]-v[10]-v[11];
    float de = v[1]-v[2]-v[4]-2.f*v[6]-v[7]+v[8]+2.f*v[9]+v[11]+v[13]-v[14];
    g_coef4[g] = make_float4(al, be, ga, de);
}

// ---------------------------------------------------------------------------
// Kernel 2: mma.sync bf16 GEMM with fused gate epilogue.
// CTA 128x128, BK=32, 5-stage cp.async, 128 threads (2x2 warps, warp tile 64x64),
// 2 CTAs/SM. Register double-buffered fragments; ONE barrier per 2 k-tiles.
#define BM 128
#define BN 128
#define BK 32
#define STAGES 5
#define LDSB 80
#define A_BYTES (BM * LDSB)           // 10240
#define B_BYTES (BN * LDSB)           // 10240
#define STG (A_BYTES + B_BYTES)       // 20480
#define DYN_SMEM (STAGES * STG)       // 102400 (x2 CTAs = 200KB/SM)
#define NKT (NIN / BK)                // 64

#define CP_ASYNC(dst, src) \
    asm volatile("cp.async.cg.shared.global [%0], [%1], 16;" :: "r"(dst), "l"(src) : "memory")
#define CP_COMMIT() asm volatile("cp.async.commit_group;" ::: "memory")
#define CP_WAIT1()  asm volatile("cp.async.wait_group 1;" ::: "memory")

__device__ __forceinline__ void ldsm4(uint32_t& r0, uint32_t& r1, uint32_t& r2, uint32_t& r3, uint32_t a) {
    asm volatile("ldmatrix.sync.aligned.m8n8.x4.shared.b16 {%0,%1,%2,%3}, [%4];"
                 : "=r"(r0), "=r"(r1), "=r"(r2), "=r"(r3) : "r"(a));
}
__device__ __forceinline__ void mma16816(float* d, const uint32_t* a, uint32_t b0, uint32_t b1) {
    asm volatile("mma.sync.aligned.m16n8k16.row.col.f32.bf16.bf16.f32 "
                 "{%0,%1,%2,%3}, {%4,%5,%6,%7}, {%8,%9}, {%0,%1,%2,%3};"
                 : "+f"(d[0]), "+f"(d[1]), "+f"(d[2]), "+f"(d[3])
                 : "r"(a[0]), "r"(a[1]), "r"(a[2]), "r"(a[3]), "r"(b0), "r"(b1));
}

__global__ __launch_bounds__(128, 2) void k_gemm(float* __restrict__ out) {
    extern __shared__ __align__(128) unsigned char dynsm[];
    const uint32_t sbase = smem_to_u32(dynsm);

    const int tid = threadIdx.x;
    const int wid = tid >> 5, lane = tid & 31;
    const int wm = wid >> 1, wn = wid & 1;      // 2x2 warp grid, warp tile 64x64
    const int bn = blockIdx.x, bm = blockIdx.y;

    const int ar = tid >> 2, ac = tid & 3;       // ar 0..31, ac 0..3
    const __nv_bfloat16* gA = g_xb + (size_t)(bm * BM + ar) * NIN + ac * 8;
    const __nv_bfloat16* gB = g_Pt + (size_t)(bn * BN + ar) * NIN + ac * 8;

    float acc[4][8][4];
#pragma unroll
    for (int mi = 0; mi < 4; ++mi)
#pragma unroll
        for (int ni = 0; ni < 8; ++ni)
#pragma unroll
            for (int q = 0; q < 4; ++q) acc[mi][ni][q] = 0.f;

    auto load_stage = [&](int slot, int t) {
        const uint32_t sa = sbase + slot * STG;
        const uint32_t sb = sa + A_BYTES;
        const int koff = t * BK;
#pragma unroll
        for (int i = 0; i < 4; ++i) {
            CP_ASYNC(sa + (ar + i * 32) * LDSB + ac * 16, gA + (size_t)(i * 32) * NIN + koff);
            CP_ASYNC(sb + (ar + i * 32) * LDSB + ac * 16, gB + (size_t)(i * 32) * NIN + koff);
        }
    };

    const uint32_t aLaneOff = (uint32_t)((lane & 15) * LDSB + (lane >> 4) * 16) + (uint32_t)(wm * 64) * LDSB;
    const uint32_t bLaneOff = (uint32_t)(((lane & 7) + ((lane >> 4) << 3)) * LDSB + ((lane >> 3) & 1) * 16)
                            + (uint32_t)(wn * 64) * LDSB + A_BYTES;

    uint32_t af[2][4][4], bf[2][4][4];

    auto load_frags = [&](int buf, int slot, uint32_t ko) {
        const uint32_t sg = sbase + slot * STG + ko;
#pragma unroll
        for (int mi = 0; mi < 4; ++mi)
            ldsm4(af[buf][mi][0], af[buf][mi][1], af[buf][mi][2], af[buf][mi][3],
                  sg + (uint32_t)(mi * 16) * LDSB + aLaneOff);
#pragma unroll
        for (int nj = 0; nj < 4; ++nj)
            ldsm4(bf[buf][nj][0], bf[buf][nj][1], bf[buf][nj][2], bf[buf][nj][3],
                  sg + (uint32_t)(nj * 16) * LDSB + bLaneOff);
    };
    auto mma_all = [&](int buf) {
#pragma unroll
        for (int mi = 0; mi < 4; ++mi)
#pragma unroll
            for (int nj = 0; nj < 4; ++nj) {
                mma16816(acc[mi][2 * nj],     af[buf][mi], bf[buf][nj][0], bf[buf][nj][1]);
                mma16816(acc[mi][2 * nj + 1], af[buf][mi], bf[buf][nj][2], bf[buf][nj][3]);
            }
    };

    // Prologue: tiles 0,1,2 into slots 0,1,2.
    load_stage(0, 0); CP_COMMIT();
    load_stage(1, 1); CP_COMMIT();
    load_stage(2, 2); CP_COMMIT();
    CP_WAIT1();                    // tiles 0,1 complete (this thread)
    __syncthreads();               // ...and visible to all
    load_frags(0, 0, 0);           // (t=0, kk=0)

    int st = 0, su = 1, sv = 2, s3 = 3, s4 = 4;   // slots of tiles t, t+1, t+2, t+3, t+4
    for (int w = 0; w < NKT / 2; ++w) {
        const int t = 2 * w;
        // Prefetch next tiles (slots freed by the PREVIOUS window's barrier).
        if (t + 3 < NKT) load_stage(s3, t + 3);
        CP_COMMIT();               // group (t+3), possibly empty at tail
        if (t + 4 < NKT) load_stage(s4, t + 4);
        CP_COMMIT();               // group (t+4), possibly empty at tail

        load_frags(1, st, 32);     // (t, kk1) — resident & visible
        mma_all(0);                // (t, kk0)
        load_frags(0, su, 0);      // (t+1, kk0) — covered by previous window's wait
        mma_all(1);                // (t, kk1)
        load_frags(1, su, 32);     // (t+1, kk1)
        mma_all(0);                // (t+1, kk0)

        CP_WAIT1();                // complete through group (t+3)
        __syncthreads();           // visible; stage reads retired before next rewrite

        load_frags(0, (t + 2 < NKT) ? sv : st, 0);  // (t+2, kk0)
        mma_all(1);                // (t+1, kk1)

        st += 2; if (st >= 5) st -= 5;
        su += 2; if (su >= 5) su -= 5;
        sv += 2; if (sv >= 5) sv -= 5;
        s3 += 2; if (s3 >= 5) s3 -= 5;
        s4 += 2; if (s4 >= 5) s4 -= 5;
    }

    // ------------------------------------------------------------------
    // Per-CTA column reciprocal table (k_rs fold).
    __syncthreads();
    float* srec = (float*)dynsm;
    {
        int j = bn * BN + tid;
        float s = 0.f;
#pragma unroll
        for (int k = 0; k < 8; ++k) s += g_spart[k * NCOL + j];
        srec[tid] = 1.f / s;
    }
    __syncthreads();

    // Epilogue in registers. Even col = A, odd col = B of gate g.
    const int row0 = bm * BM + wm * 64 + (lane >> 2);
    const int lg0 = wn * 32 + (lane & 3);
    const int gbase = bn * (BN / 2) + lg0;
#pragma unroll
    for (int ni = 0; ni < 8; ++ni) {
        const int g = gbase + ni * 4;
        const float2 rsv = *(const float2*)(srec + 2 * (lg0 + ni * 4));
        const float4 cf = g_coef4[g];
#pragma unroll
        for (int mi = 0; mi < 4; ++mi) {
            const float* d = acc[mi][ni];
            float Av = d[0] * rsv.x, Bv = d[1] * rsv.y;
            out[(size_t)(row0 + mi * 16) * NG + g] =
                cf.x + cf.y * Av + cf.z * Bv + cf.w * (Av * Bv);
            Av = d[2] * rsv.x; Bv = d[3] * rsv.y;
            out[(size_t)(row0 + mi * 16 + 8) * NG + g] =
                cf.x + cf.y * Av + cf.z * Bv + cf.w * (Av * Bv);
        }
    }
}

// ---------------------------------------------------------------------------
extern "C" void kernel_launch(void* const* d_in, const int* in_sizes, int n_in,
                              void* d_out, int out_size) {
    const float* x = (const float*)d_in[0];  // (2048, 2048)
    const float* w = (const float*)d_in[1];  // (16, 8192)
    const float* c = (const float*)d_in[2];  // (2048, 8192, 2)
    float* out = (float*)d_out;              // (2048, 8192)

    cudaFuncSetAttribute(k_gemm, cudaFuncAttributeMaxDynamicSharedMemorySize, DYN_SMEM);

    k_fuse<<<NB_EXP + NB_XCVT + NG / 256, 256>>>(c, x, w);
    k_gemm<<<dim3(NCOL / BN, BATCH / BM), 128, DYN_SMEM>>>(out);
}

// round 14
// speedup vs baseline: 1.0543x; 1.0543x over previous
#include <cuda_runtime.h>
#include <cuda_bf16.h>
#include <cstdint>

#define BATCH 2048
#define NIN   2048
#define NG    8192
#define NCOL  16384  // NG*2

// ---------------------------------------------------------------------------
// Scratch (static device globals -- allocation-free rule)
__device__ __align__(1024) __nv_bfloat16 g_Pt[(size_t)NCOL * NIN];  // exp(c)^T, 67 MB
__device__ __align__(1024) __nv_bfloat16 g_xb[(size_t)BATCH * NIN]; // x bf16, 8 MB
__device__ float  g_spart[8 * NCOL];
__device__ float4 g_coef4[NG];     // (alpha, beta, gamma, delta) per gate

__device__ __forceinline__ uint32_t smem_to_u32(const void* p) {
    uint32_t a;
    asm("{ .reg .u64 t; cvta.to.shared.u64 t, %1; cvt.u32.u64 %0, t; }" : "=r"(a) : "l"(p));
    return a;
}

// ---------------------------------------------------------------------------
// Kernel 1: fused Pt=exp(c)^T (+ partial sums), x->bf16 cast, gate coefficients.
// Vectorized: exp path reads float2 (64-j tile), xcvt path reads float4.
#define NB_EXP  2048   // (NCOL/64) * (NIN/256) = 256 * 8
#define NB_XCVT 4096   // BATCH*NIN/1024
__global__ __launch_bounds__(256) void k_fuse(const float* __restrict__ c,
                                              const float* __restrict__ x,
                                              const float* __restrict__ w) {
    int b = blockIdx.x;
    if (b < NB_EXP) {
        __shared__ __nv_bfloat16 sm[256][66];   // [i][j], 66 pad: stride 33 words
        __shared__ float ssum[8][64];
        const int bx = b & 255, by = b >> 8;
        const int tj = threadIdx.x & 31;        // j-pair index
        const int ti = threadIdx.x >> 5;
        const int j0 = bx * 64;
        const int i0 = by * 256;

        float s0 = 0.f, s1 = 0.f;
#pragma unroll 4
        for (int it = 0; it < 32; ++it) {
            int il = ti + 8 * it;
            float2 rd = *(const float2*)(c + (size_t)(i0 + il) * NCOL + j0 + 2 * tj);
            float e0 = __expf(rd.x), e1 = __expf(rd.y);
            __nv_bfloat162 pk = __floats2bfloat162_rn(e0, e1);
            *(__nv_bfloat162*)(&sm[il][2 * tj]) = pk;
            s0 += e0; s1 += e1;
        }
        ssum[ti][2 * tj] = s0;
        ssum[ti][2 * tj + 1] = s1;
        __syncthreads();
        if (threadIdx.x < 64) {
            float t = 0.f;
#pragma unroll
            for (int k = 0; k < 8; ++k) t += ssum[k][threadIdx.x];
            g_spart[by * NCOL + j0 + threadIdx.x] = t;
        }
        // transposed write: 64 j-rows, 256 i contiguous each (512B/row)
#pragma unroll 4
        for (int jj = 0; jj < 64; ++jj) {
            g_Pt[(size_t)(j0 + jj) * NIN + i0 + threadIdx.x] = sm[threadIdx.x][jj];
        }
        return;
    }
    if (b < NB_EXP + NB_XCVT) {
        int i = ((b - NB_EXP) * 256 + threadIdx.x) * 4;
        float4 rd = *(const float4*)(x + i);
        __nv_bfloat162 p0 = __floats2bfloat162_rn(rd.x, rd.y);
        __nv_bfloat162 p1 = __floats2bfloat162_rn(rd.z, rd.w);
        *(__nv_bfloat162*)(g_xb + i)     = p0;
        *(__nv_bfloat162*)(g_xb + i + 2) = p1;
        return;
    }
    int g = (b - NB_EXP - NB_XCVT) * 256 + threadIdx.x;
    if (g >= NG) return;
    float v[16];
    float m = -1e30f;
#pragma unroll
    for (int k = 0; k < 16; ++k) { v[k] = w[k * NG + g]; m = fmaxf(m, v[k]); }
    float sum = 0.f;
#pragma unroll
    for (int k = 0; k < 16; ++k) { v[k] = __expf(v[k] - m); sum += v[k]; }
    float inv = 1.f / sum;
#pragma unroll
    for (int k = 0; k < 16; ++k) v[k] *= inv;

    float al = v[8]+v[9]+v[10]+v[11]+v[12]+v[13]+v[14]+v[15];
    float be = v[2]+v[3]+v[6]+v[7] - v[8]-v[9]-v[12]-v[13];
    float ga = v[4]+v[5]+v[6]+v[7] - v[8]-v[9]-v[10]-v[11];
    float de = v[1]-v[2]-v[4]-2.f*v[6]-v[7]+v[8]+2.f*v[9]+v[11]+v[13]-v[14];
    g_coef4[g] = make_float4(al, be, ga, de);
}

// ---------------------------------------------------------------------------
// Kernel 2: mma.sync bf16 GEMM with fused gate epilogue. (R12 structure — best)
// CTA 128x128, BK=32, 4-stage cp.async, 128 threads (2x2 warps, warp tile 64x64),
// 2 CTAs/SM. Register double-buffered fragments with cross-tile prefetch.
#define BM 128
#define BN 128
#define BK 32
#define STAGES 4
#define LDSB 80
#define A_BYTES (BM * LDSB)           // 10240
#define B_BYTES (BN * LDSB)           // 10240
#define STG (A_BYTES + B_BYTES)       // 20480
#define DYN_SMEM (STAGES * STG)       // 81920 (x2 CTAs = 160KB/SM)
#define NKT (NIN / BK)                // 64

#define CP_ASYNC(dst, src) \
    asm volatile("cp.async.cg.shared.global [%0], [%1], 16;" :: "r"(dst), "l"(src) : "memory")
#define CP_COMMIT() asm volatile("cp.async.commit_group;" ::: "memory")
#define CP_WAIT2()  asm volatile("cp.async.wait_group 2;" ::: "memory")

__device__ __forceinline__ void ldsm4(uint32_t& r0, uint32_t& r1, uint32_t& r2, uint32_t& r3, uint32_t a) {
    asm volatile("ldmatrix.sync.aligned.m8n8.x4.shared.b16 {%0,%1,%2,%3}, [%4];"
                 : "=r"(r0), "=r"(r1), "=r"(r2), "=r"(r3) : "r"(a));
}
__device__ __forceinline__ void mma16816(float* d, const uint32_t* a, uint32_t b0, uint32_t b1) {
    asm volatile("mma.sync.aligned.m16n8k16.row.col.f32.bf16.bf16.f32 "
                 "{%0,%1,%2,%3}, {%4,%5,%6,%7}, {%8,%9}, {%0,%1,%2,%3};"
                 : "+f"(d[0]), "+f"(d[1]), "+f"(d[2]), "+f"(d[3])
                 : "r"(a[0]), "r"(a[1]), "r"(a[2]), "r"(a[3]), "r"(b0), "r"(b1));
}

__global__ __launch_bounds__(128, 2) void k_gemm(float* __restrict__ out) {
    extern __shared__ __align__(128) unsigned char dynsm[];
    const uint32_t sbase = smem_to_u32(dynsm);

    const int tid = threadIdx.x;
    const int wid = tid >> 5, lane = tid & 31;
    const int wm = wid >> 1, wn = wid & 1;      // 2x2 warp grid, warp tile 64x64
    const int bn = blockIdx.x, bm = blockIdx.y;

    const int ar = tid >> 2, ac = tid & 3;       // ar 0..31, ac 0..3
    const __nv_bfloat16* gA = g_xb + (size_t)(bm * BM + ar) * NIN + ac * 8;
    const __nv_bfloat16* gB = g_Pt + (size_t)(bn * BN + ar) * NIN + ac * 8;

    float acc[4][8][4];
#pragma unroll
    for (int mi = 0; mi < 4; ++mi)
#pragma unroll
        for (int ni = 0; ni < 8; ++ni)
#pragma unroll
            for (int q = 0; q < 4; ++q) acc[mi][ni][q] = 0.f;

    auto load_stage = [&](int s, int t) {
        const uint32_t sa = sbase + s * STG;
        const uint32_t sb = sa + A_BYTES;
        const int koff = t * BK;
#pragma unroll
        for (int i = 0; i < 4; ++i) {
            CP_ASYNC(sa + (ar + i * 32) * LDSB + ac * 16, gA + (size_t)(i * 32) * NIN + koff);
            CP_ASYNC(sb + (ar + i * 32) * LDSB + ac * 16, gB + (size_t)(i * 32) * NIN + koff);
        }
    };

    const uint32_t aLaneOff = (uint32_t)((lane & 15) * LDSB + (lane >> 4) * 16) + (uint32_t)(wm * 64) * LDSB;
    const uint32_t bLaneOff = (uint32_t)(((lane & 7) + ((lane >> 4) << 3)) * LDSB + ((lane >> 3) & 1) * 16)
                            + (uint32_t)(wn * 64) * LDSB + A_BYTES;

    uint32_t af[2][4][4], bf[2][4][4];

    auto load_frags = [&](int buf, int t, uint32_t ko) {
        const uint32_t sg = sbase + (t % STAGES) * STG + ko;
#pragma unroll
        for (int mi = 0; mi < 4; ++mi)
            ldsm4(af[buf][mi][0], af[buf][mi][1], af[buf][mi][2], af[buf][mi][3],
                  sg + (uint32_t)(mi * 16) * LDSB + aLaneOff);
#pragma unroll
        for (int nj = 0; nj < 4; ++nj)
            ldsm4(bf[buf][nj][0], bf[buf][nj][1], bf[buf][nj][2], bf[buf][nj][3],
                  sg + (uint32_t)(nj * 16) * LDSB + bLaneOff);
    };
    auto mma_all = [&](int buf) {
#pragma unroll
        for (int mi = 0; mi < 4; ++mi)
#pragma unroll
            for (int nj = 0; nj < 4; ++nj) {
                mma16816(acc[mi][2 * nj],     af[buf][mi], bf[buf][nj][0], bf[buf][nj][1]);
                mma16816(acc[mi][2 * nj + 1], af[buf][mi], bf[buf][nj][2], bf[buf][nj][3]);
            }
    };

#pragma unroll
    for (int s = 0; s < STAGES - 1; ++s) { load_stage(s, s); CP_COMMIT(); }
    CP_WAIT2();                    // stage 0 complete (this thread)
    __syncthreads();               // stage 0 visible to all
    load_frags(0, 0, 0);           // frags (t=0, kk=0)

    for (int t = 0; t < NKT; ++t) {
        load_frags(1, t, 32);      // (t, kk=1); stage t visible since last sync
        mma_all(0);                // consume frags prefetched last window

        if (t + STAGES - 1 < NKT) load_stage((t + STAGES - 1) % STAGES, t + STAGES - 1);
        CP_COMMIT();
        CP_WAIT2();                // stage t+1 complete (pending = {t+2, t+3})
        __syncthreads();           // stage t+1 visible; stage-t reads retired before rewrite

        const int tn = (t + 1 < NKT) ? t + 1 : t;
        load_frags(0, tn, 0);      // prefetch (t+1, kk=0)
        mma_all(1);
    }

    // ------------------------------------------------------------------
    // Per-CTA column reciprocal table (k_rs fold).
    __syncthreads();
    float* srec = (float*)dynsm;
    {
        int j = bn * BN + tid;
        float s = 0.f;
#pragma unroll
        for (int k = 0; k < 8; ++k) s += g_spart[k * NCOL + j];
        srec[tid] = 1.f / s;
    }
    __syncthreads();

    // Epilogue in registers. Even col = A, odd col = B of gate g.
    const int row0 = bm * BM + wm * 64 + (lane >> 2);
    const int lg0 = wn * 32 + (lane & 3);
    const int gbase = bn * (BN / 2) + lg0;
#pragma unroll
    for (int ni = 0; ni < 8; ++ni) {
        const int g = gbase + ni * 4;
        const float2 rsv = *(const float2*)(srec + 2 * (lg0 + ni * 4));
        const float4 cf = g_coef4[g];
#pragma unroll
        for (int mi = 0; mi < 4; ++mi) {
            const float* d = acc[mi][ni];
            float Av = d[0] * rsv.x, Bv = d[1] * rsv.y;
            out[(size_t)(row0 + mi * 16) * NG + g] =
                cf.x + cf.y * Av + cf.z * Bv + cf.w * (Av * Bv);
            Av = d[2] * rsv.x; Bv = d[3] * rsv.y;
            out[(size_t)(row0 + mi * 16 + 8) * NG + g] =
                cf.x + cf.y * Av + cf.z * Bv + cf.w * (Av * Bv);
        }
    }
}

// ---------------------------------------------------------------------------
extern "C" void kernel_launch(void* const* d_in, const int* in_sizes, int n_in,
                              void* d_out, int out_size) {
    const float* x = (const float*)d_in[0];  // (2048, 2048)
    const float* w = (const float*)d_in[1];  // (16, 8192)
    const float* c = (const float*)d_in[2];  // (2048, 8192, 2)
    float* out = (float*)d_out;              // (2048, 8192)

    cudaFuncSetAttribute(k_gemm, cudaFuncAttributeMaxDynamicSharedMemorySize, DYN_SMEM);

    k_fuse<<<NB_EXP + NB_XCVT + NG / 256, 256>>>(c, x, w);
    k_gemm<<<dim3(NCOL / BN, BATCH / BM), 128, DYN_SMEM>>>(out);
}

// round 15
// speedup vs baseline: 1.0591x; 1.0045x over previous
#include <cuda_runtime.h>
#include <cuda_bf16.h>
#include <cstdint>

#define BATCH 2048
#define NIN   2048
#define NG    8192
#define NCOL  16384  // NG*2

// ---------------------------------------------------------------------------
// Scratch (static device globals -- allocation-free rule)
__device__ __align__(1024) __nv_bfloat16 g_Pt[(size_t)NCOL * NIN];  // exp(c)^T, 67 MB
__device__ __align__(1024) __nv_bfloat16 g_xb[(size_t)BATCH * NIN]; // x bf16, 8 MB
__device__ float  g_spart[8 * NCOL];
__device__ float4 g_coef4[NG];     // (alpha, beta, gamma, delta) per gate

__device__ __forceinline__ uint32_t smem_to_u32(const void* p) {
    uint32_t a;
    asm("{ .reg .u64 t; cvta.to.shared.u64 t, %1; cvt.u32.u64 %0, t; }" : "=r"(a) : "l"(p));
    return a;
}

// ---------------------------------------------------------------------------
// Kernel 1: fused Pt=exp(c)^T (+ partial sums), x->bf16 cast, gate coefficients.
// exp path: [j][i] smem staging -> bf16x2 gmem stores (half the STG count).
#define NB_EXP  2048   // (NCOL/64) * (NIN/256) = 256 * 8
#define NB_XCVT 4096   // BATCH*NIN/1024
__global__ __launch_bounds__(256) void k_fuse(const float* __restrict__ c,
                                              const float* __restrict__ x,
                                              const float* __restrict__ w) {
    int b = blockIdx.x;
    if (b < NB_EXP) {
        __shared__ __nv_bfloat16 sm[64][258];   // [j][i], row stride 258 (129 words, odd)
        __shared__ float ssum[8][64];
        const int bx = b & 255, by = b >> 8;
        const int tj = threadIdx.x & 31;        // j-pair index
        const int ti = threadIdx.x >> 5;
        const int j0 = bx * 64;
        const int i0 = by * 256;

        float s0 = 0.f, s1 = 0.f;
#pragma unroll 8
        for (int it = 0; it < 32; ++it) {
            int il = ti + 8 * it;
            float2 rd = *(const float2*)(c + (size_t)(i0 + il) * NCOL + j0 + 2 * tj);
            float e0 = __expf(rd.x), e1 = __expf(rd.y);
            sm[2 * tj][il]     = __float2bfloat16(e0);
            sm[2 * tj + 1][il] = __float2bfloat16(e1);
            s0 += e0; s1 += e1;
        }
        ssum[ti][2 * tj] = s0;
        ssum[ti][2 * tj + 1] = s1;
        __syncthreads();
        if (threadIdx.x < 64) {
            float t = 0.f;
#pragma unroll
            for (int k = 0; k < 8; ++k) t += ssum[k][threadIdx.x];
            g_spart[by * NCOL + j0 + threadIdx.x] = t;
        }
        // transposed write: 2 j-rows per iteration, 4B bf16x2 stores, CF smem reads
        const int jsel = threadIdx.x >> 7;          // 0/1: which of the 2 rows
        const int ih = (threadIdx.x & 127) * 2;     // i offset (even)
#pragma unroll 8
        for (int jp = 0; jp < 32; ++jp) {
            const int jrow = 2 * jp + jsel;
            __nv_bfloat162 pk;
            pk.x = sm[jrow][ih];
            pk.y = sm[jrow][ih + 1];
            *(__nv_bfloat162*)(g_Pt + (size_t)(j0 + jrow) * NIN + i0 + ih) = pk;
        }
        return;
    }
    if (b < NB_EXP + NB_XCVT) {
        int i = ((b - NB_EXP) * 256 + threadIdx.x) * 4;
        float4 rd = *(const float4*)(x + i);
        __nv_bfloat162 p0 = __floats2bfloat162_rn(rd.x, rd.y);
        __nv_bfloat162 p1 = __floats2bfloat162_rn(rd.z, rd.w);
        *(__nv_bfloat162*)(g_xb + i)     = p0;
        *(__nv_bfloat162*)(g_xb + i + 2) = p1;
        return;
    }
    int g = (b - NB_EXP - NB_XCVT) * 256 + threadIdx.x;
    if (g >= NG) return;
    float v[16];
    float m = -1e30f;
#pragma unroll
    for (int k = 0; k < 16; ++k) { v[k] = w[k * NG + g]; m = fmaxf(m, v[k]); }
    float sum = 0.f;
#pragma unroll
    for (int k = 0; k < 16; ++k) { v[k] = __expf(v[k] - m); sum += v[k]; }
    float inv = 1.f / sum;
#pragma unroll
    for (int k = 0; k < 16; ++k) v[k] *= inv;

    float al = v[8]+v[9]+v[10]+v[11]+v[12]+v[13]+v[14]+v[15];
    float be = v[2]+v[3]+v[6]+v[7] - v[8]-v[9]-v[12]-v[13];
    float ga = v[4]+v[5]+v[6]+v[7] - v[8]-v[9]-v[10]-v[11];
    float de = v[1]-v[2]-v[4]-2.f*v[6]-v[7]+v[8]+2.f*v[9]+v[11]+v[13]-v[14];
    g_coef4[g] = make_float4(al, be, ga, de);
}

// ---------------------------------------------------------------------------
// Kernel 2: mma.sync bf16 GEMM with fused gate epilogue. (R12 structure — best)
// CTA 128x128, BK=32, 4-stage cp.async, 128 threads (2x2 warps, warp tile 64x64),
// 2 CTAs/SM. Register double-buffered fragments; loads issued before MMA burst.
#define BM 128
#define BN 128
#define BK 32
#define STAGES 4
#define LDSB 80
#define A_BYTES (BM * LDSB)           // 10240
#define B_BYTES (BN * LDSB)           // 10240
#define STG (A_BYTES + B_BYTES)       // 20480
#define DYN_SMEM (STAGES * STG)       // 81920 (x2 CTAs = 160KB/SM)
#define NKT (NIN / BK)                // 64

#define CP_ASYNC(dst, src) \
    asm volatile("cp.async.cg.shared.global [%0], [%1], 16;" :: "r"(dst), "l"(src) : "memory")
#define CP_COMMIT() asm volatile("cp.async.commit_group;" ::: "memory")
#define CP_WAIT2()  asm volatile("cp.async.wait_group 2;" ::: "memory")

__device__ __forceinline__ void ldsm4(uint32_t& r0, uint32_t& r1, uint32_t& r2, uint32_t& r3, uint32_t a) {
    asm volatile("ldmatrix.sync.aligned.m8n8.x4.shared.b16 {%0,%1,%2,%3}, [%4];"
                 : "=r"(r0), "=r"(r1), "=r"(r2), "=r"(r3) : "r"(a));
}
__device__ __forceinline__ void mma16816(float* d, const uint32_t* a, uint32_t b0, uint32_t b1) {
    asm volatile("mma.sync.aligned.m16n8k16.row.col.f32.bf16.bf16.f32 "
                 "{%0,%1,%2,%3}, {%4,%5,%6,%7}, {%8,%9}, {%0,%1,%2,%3};"
                 : "+f"(d[0]), "+f"(d[1]), "+f"(d[2]), "+f"(d[3])
                 : "r"(a[0]), "r"(a[1]), "r"(a[2]), "r"(a[3]), "r"(b0), "r"(b1));
}

__global__ __launch_bounds__(128, 2) void k_gemm(float* __restrict__ out) {
    extern __shared__ __align__(128) unsigned char dynsm[];
    const uint32_t sbase = smem_to_u32(dynsm);

    const int tid = threadIdx.x;
    const int wid = tid >> 5, lane = tid & 31;
    const int wm = wid >> 1, wn = wid & 1;      // 2x2 warp grid, warp tile 64x64
    const int bn = blockIdx.x, bm = blockIdx.y;

    const int ar = tid >> 2, ac = tid & 3;       // ar 0..31, ac 0..3
    const __nv_bfloat16* gA = g_xb + (size_t)(bm * BM + ar) * NIN + ac * 8;
    const __nv_bfloat16* gB = g_Pt + (size_t)(bn * BN + ar) * NIN + ac * 8;

    float acc[4][8][4];
#pragma unroll
    for (int mi = 0; mi < 4; ++mi)
#pragma unroll
        for (int ni = 0; ni < 8; ++ni)
#pragma unroll
            for (int q = 0; q < 4; ++q) acc[mi][ni][q] = 0.f;

    auto load_stage = [&](int s, int t) {
        const uint32_t sa = sbase + s * STG;
        const uint32_t sb = sa + A_BYTES;
        const int koff = t * BK;
#pragma unroll
        for (int i = 0; i < 4; ++i) {
            CP_ASYNC(sa + (ar + i * 32) * LDSB + ac * 16, gA + (size_t)(i * 32) * NIN + koff);
            CP_ASYNC(sb + (ar + i * 32) * LDSB + ac * 16, gB + (size_t)(i * 32) * NIN + koff);
        }
    };

    const uint32_t aLaneOff = (uint32_t)((lane & 15) * LDSB + (lane >> 4) * 16) + (uint32_t)(wm * 64) * LDSB;
    const uint32_t bLaneOff = (uint32_t)(((lane & 7) + ((lane >> 4) << 3)) * LDSB + ((lane >> 3) & 1) * 16)
                            + (uint32_t)(wn * 64) * LDSB + A_BYTES;

    uint32_t af[2][4][4], bf[2][4][4];

    auto load_frags = [&](int buf, int t, uint32_t ko) {
        const uint32_t sg = sbase + (t % STAGES) * STG + ko;
#pragma unroll
        for (int mi = 0; mi < 4; ++mi)
            ldsm4(af[buf][mi][0], af[buf][mi][1], af[buf][mi][2], af[buf][mi][3],
                  sg + (uint32_t)(mi * 16) * LDSB + aLaneOff);
#pragma unroll
        for (int nj = 0; nj < 4; ++nj)
            ldsm4(bf[buf][nj][0], bf[buf][nj][1], bf[buf][nj][2], bf[buf][nj][3],
                  sg + (uint32_t)(nj * 16) * LDSB + bLaneOff);
    };
    auto mma_all = [&](int buf) {
#pragma unroll
        for (int mi = 0; mi < 4; ++mi)
#pragma unroll
            for (int nj = 0; nj < 4; ++nj) {
                mma16816(acc[mi][2 * nj],     af[buf][mi], bf[buf][nj][0], bf[buf][nj][1]);
                mma16816(acc[mi][2 * nj + 1], af[buf][mi], bf[buf][nj][2], bf[buf][nj][3]);
            }
    };

#pragma unroll
    for (int s = 0; s < STAGES - 1; ++s) { load_stage(s, s); CP_COMMIT(); }
    CP_WAIT2();                    // stage 0 complete (this thread)
    __syncthreads();               // stage 0 visible to all
    load_frags(0, 0, 0);           // frags (t=0, kk=0)

    for (int t = 0; t < NKT; ++t) {
        load_frags(1, t, 32);      // (t, kk=1); stage t visible since last sync

        // issue next stage's cp.asyncs BEFORE the MMA burst (more slack for wait)
        if (t + STAGES - 1 < NKT) load_stage((t + STAGES - 1) % STAGES, t + STAGES - 1);
        CP_COMMIT();

        mma_all(0);                // consume frags prefetched last window

        CP_WAIT2();                // stage t+1 complete (pending = {t+2, t+3})
        __syncthreads();           // stage t+1 visible; stage-t reads retired before rewrite

        const int tn = (t + 1 < NKT) ? t + 1 : t;
        load_frags(0, tn, 0);      // prefetch (t+1, kk=0)
        mma_all(1);
    }

    // ------------------------------------------------------------------
    // Per-CTA column reciprocal table (k_rs fold).
    __syncthreads();
    float* srec = (float*)dynsm;
    {
        int j = bn * BN + tid;
        float s = 0.f;
#pragma unroll
        for (int k = 0; k < 8; ++k) s += g_spart[k * NCOL + j];
        srec[tid] = 1.f / s;
    }
    __syncthreads();

    // Epilogue in registers. Even col = A, odd col = B of gate g.
    const int row0 = bm * BM + wm * 64 + (lane >> 2);
    const int lg0 = wn * 32 + (lane & 3);
    const int gbase = bn * (BN / 2) + lg0;
#pragma unroll
    for (int ni = 0; ni < 8; ++ni) {
        const int g = gbase + ni * 4;
        const float2 rsv = *(const float2*)(srec + 2 * (lg0 + ni * 4));
        const float4 cf = g_coef4[g];
#pragma unroll
        for (int mi = 0; mi < 4; ++mi) {
            const float* d = acc[mi][ni];
            float Av = d[0] * rsv.x, Bv = d[1] * rsv.y;
            out[(size_t)(row0 + mi * 16) * NG + g] =
                cf.x + cf.y * Av + cf.z * Bv + cf.w * (Av * Bv);
            Av = d[2] * rsv.x; Bv = d[3] * rsv.y;
            out[(size_t)(row0 + mi * 16 + 8) * NG + g] =
                cf.x + cf.y * Av + cf.z * Bv + cf.w * (Av * Bv);
        }
    }
}

// ---------------------------------------------------------------------------
extern "C" void kernel_launch(void* const* d_in, const int* in_sizes, int n_in,
                              void* d_out, int out_size) {
    const float* x = (const float*)d_in[0];  // (2048, 2048)
    const float* w = (const float*)d_in[1];  // (16, 8192)
    const float* c = (const float*)d_in[2];  // (2048, 8192, 2)
    float* out = (float*)d_out;              // (2048, 8192)

    cudaFuncSetAttribute(k_gemm, cudaFuncAttributeMaxDynamicSharedMemorySize, DYN_SMEM);

    k_fuse<<<NB_EXP + NB_XCVT + NG / 256, 256>>>(c, x, w);
    k_gemm<<<dim3(NCOL / BN, BATCH / BM), 128, DYN_SMEM>>>(out);
}